// round 1
// baseline (speedup 1.0000x reference)
#include <cuda_runtime.h>

// Problem constants
constexpr int B_   = 4;
constexpr int T_   = 16;
constexpr int C_   = 256;
constexpr int HEADS = 8;
constexpr int DH   = 32;        // dim_head
constexpr int HW   = 1024;      // 32*32 spatial
constexpr int NSLAB = B_ * T_;  // 64 (b,t) slabs
constexpr float QSCALE = 0.17677669529663687f; // 32^-0.5

// Scratch (allocation-free: __device__ globals)
// q/k/v layout: [b][head][t][d][hw]  (hw contiguous)
__device__ float g_q[B_ * HEADS * T_ * DH * HW];
__device__ float g_k[B_ * HEADS * T_ * DH * HW];
__device__ float g_v[B_ * HEADS * T_ * DH * HW];
// attention output layout: [bt][e=head*32+d][hw]
__device__ float g_o[NSLAB * C_ * HW];

// ---------------- packed fp32x2 helpers (sm_100+) ----------------
__device__ __forceinline__ unsigned long long pack2(float lo, float hi) {
    unsigned long long r;
    asm("mov.b64 %0, {%1, %2};" : "=l"(r) : "f"(lo), "f"(hi));
    return r;
}
__device__ __forceinline__ void unpack2(unsigned long long p, float& lo, float& hi) {
    asm("mov.b64 {%0, %1}, %2;" : "=f"(lo), "=f"(hi) : "l"(p));
}
__device__ __forceinline__ unsigned long long ffma2(unsigned long long a,
                                                    unsigned long long b,
                                                    unsigned long long c) {
    unsigned long long d;
    asm("fma.rn.f32x2 %0, %1, %2, %3;" : "=l"(d) : "l"(a), "l"(b), "l"(c));
    return d;
}

// ---------------- GEMM: per-slab  Out[N,1024] = W[N,256] @ X[256,1024] ----------------
// Block tile: 64(n) x 128(m), BK=16, 256 threads, microtile 4(n) x 8(m)
// EPI==0: QKV epilogue (route o -> q/k/v buffers, +bias, q*scale)
// EPI==1: plain epilogue (+bias) into Y (= d_out, already correct layout)
template <int EPI>
__global__ __launch_bounds__(256) void gemm_k(const float* __restrict__ W,
                                              const float* __restrict__ Xin,
                                              const float* __restrict__ bias,
                                              float* __restrict__ Y) {
    __shared__ __align__(16) float a_s[16][64];    // [k][n]
    __shared__ __align__(16) float b_s[16][128];   // [k][m]

    const int slab = blockIdx.z;          // bt = b*16 + t
    const int n0 = blockIdx.y * 64;
    const int m0 = blockIdx.x * 128;
    const int tid = threadIdx.x;
    const int tx = tid & 15;              // m group
    const int ty = tid >> 4;              // n group

    const float* Xs = (EPI == 1 ? (const float*)g_o : Xin) + (size_t)slab * C_ * HW;

    // global load mapping
    const int na = tid >> 2;              // 0..63
    const int ka = (tid & 3) * 4;         // 0,4,8,12
    const int kb = tid >> 4;              // 0..15
    const int mb = (tid & 15) * 8;        // 0..120
    const float* aptr = W + (size_t)(n0 + na) * C_ + ka;
    const float* bptr = Xs + (size_t)kb * HW + m0 + mb;

    unsigned long long acc[4][4];
#pragma unroll
    for (int r = 0; r < 4; r++)
#pragma unroll
        for (int p = 0; p < 4; p++) acc[r][p] = 0ull;

    float4 ra  = *(const float4*)aptr;
    float4 rb0 = *(const float4*)bptr;
    float4 rb1 = *(const float4*)(bptr + 4);

    for (int kt = 0; kt < 16; kt++) {
        // store staged tile (A transposed to [k][n])
        a_s[ka + 0][na] = ra.x;
        a_s[ka + 1][na] = ra.y;
        a_s[ka + 2][na] = ra.z;
        a_s[ka + 3][na] = ra.w;
        *(float4*)&b_s[kb][mb]     = rb0;
        *(float4*)&b_s[kb][mb + 4] = rb1;
        __syncthreads();

        if (kt < 15) {
            ra  = *(const float4*)(aptr + (kt + 1) * 16);
            rb0 = *(const float4*)(bptr + (size_t)(kt + 1) * 16 * HW);
            rb1 = *(const float4*)(bptr + (size_t)(kt + 1) * 16 * HW + 4);
        }

#pragma unroll
        for (int k = 0; k < 16; k++) {
            const ulonglong2 bg0 = *(const ulonglong2*)&b_s[k][tx * 4];
            const ulonglong2 bg1 = *(const ulonglong2*)&b_s[k][64 + tx * 4];
#pragma unroll
            for (int r = 0; r < 4; r++) {
                const float a = a_s[k][ty * 4 + r];
                const unsigned long long aa = pack2(a, a);
                acc[r][0] = ffma2(aa, bg0.x, acc[r][0]);
                acc[r][1] = ffma2(aa, bg0.y, acc[r][1]);
                acc[r][2] = ffma2(aa, bg1.x, acc[r][2]);
                acc[r][3] = ffma2(aa, bg1.y, acc[r][3]);
            }
        }
        __syncthreads();
    }

    // epilogue
    const int b_ = slab >> 4;   // b
    const int t_ = slab & 15;   // t
#pragma unroll
    for (int r = 0; r < 4; r++) {
        const int o = n0 + ty * 4 + r;
        float c0, c1, c2, c3, c4, c5, c6, c7;
        unpack2(acc[r][0], c0, c1);
        unpack2(acc[r][1], c2, c3);
        unpack2(acc[r][2], c4, c5);
        unpack2(acc[r][3], c6, c7);
        const float bv = bias[o];
        if (EPI == 0) {
            const int which = o >> 8;       // 0=q 1=k 2=v
            const int rem = o & 255;
            const int head = rem >> 5;
            const int d = rem & 31;
            float* dst;
            float sc = 1.0f;
            if (which == 0) { dst = g_q; sc = QSCALE; }
            else if (which == 1) { dst = g_k; }
            else { dst = g_v; }
            const size_t base =
                ((size_t)(((b_ * HEADS + head) * T_ + t_) * DH + d)) * HW + m0;
            float4 w0 = make_float4((c0 + bv) * sc, (c1 + bv) * sc,
                                    (c2 + bv) * sc, (c3 + bv) * sc);
            float4 w1 = make_float4((c4 + bv) * sc, (c5 + bv) * sc,
                                    (c6 + bv) * sc, (c7 + bv) * sc);
            *(float4*)(dst + base + tx * 4)      = w0;
            *(float4*)(dst + base + 64 + tx * 4) = w1;
        } else {
            float* dst = Y + ((size_t)slab * C_ + o) * HW + m0;
            float4 w0 = make_float4(c0 + bv, c1 + bv, c2 + bv, c3 + bv);
            float4 w1 = make_float4(c4 + bv, c5 + bv, c6 + bv, c7 + bv);
            *(float4*)(dst + tx * 4)      = w0;
            *(float4*)(dst + 64 + tx * 4) = w1;
        }
    }
}

// ---------------- Attention over T=16 per (b, head, hw) ----------------
// Block: one (b*8+head, hw tile of 8). 128 threads = 8(hw) x 16(i=query t).
__global__ __launch_bounds__(128) void attn_k(const float* __restrict__ rel_pos) {
    __shared__ float k_s[16 * 32 * 8];  // [t*32+d][hw] 16KB
    __shared__ float v_s[16 * 32 * 8];

    const int bh  = blockIdx.y;            // b*8 + head
    const int hw0 = blockIdx.x * 8;
    const int tid = threadIdx.x;
    const int hwl = tid & 7;
    const int i   = tid >> 3;              // query time index 0..15

    const size_t ubase = (size_t)bh * 512 * HW;  // 512 = T*DH rows of 1024

    for (int e = tid; e < 4096; e += 128) {
        const int td = e >> 3;
        const int hw = e & 7;
        k_s[e] = g_k[ubase + (size_t)td * HW + hw0 + hw];
        v_s[e] = g_v[ubase + (size_t)td * HW + hw0 + hw];
    }
    __syncthreads();

    float q[32];
    const size_t qbase = ubase + (size_t)i * 32 * HW + hw0 + hwl;
#pragma unroll
    for (int d = 0; d < 32; d++) q[d] = g_q[qbase + (size_t)d * HW];

    const int head = bh & 7;
    const float* rp = rel_pos + head * 256 + i * 16;

    float s[16];
#pragma unroll
    for (int j = 0; j < 16; j++) {
        float acc = 0.0f;
#pragma unroll
        for (int d = 0; d < 32; d++) acc += q[d] * k_s[(j * 32 + d) * 8 + hwl];
        s[j] = acc + rp[j];
    }

    float mx = s[0];
#pragma unroll
    for (int j = 1; j < 16; j++) mx = fmaxf(mx, s[j]);
    float sum = 0.0f;
#pragma unroll
    for (int j = 0; j < 16; j++) { s[j] = expf(s[j] - mx); sum += s[j]; }
    const float inv = 1.0f / sum;

    const int b_ = bh >> 3;
    const size_t obase =
        ((size_t)((b_ * 16 + i) * 256 + head * 32)) * HW + hw0 + hwl;
#pragma unroll
    for (int d = 0; d < 32; d++) {
        float acc = 0.0f;
#pragma unroll
        for (int j = 0; j < 16; j++) acc += s[j] * v_s[(j * 32 + d) * 8 + hwl];
        g_o[obase + (size_t)d * HW] = acc * inv;
    }
}

extern "C" void kernel_launch(void* const* d_in, const int* in_sizes, int n_in,
                              void* d_out, int out_size) {
    const float* x       = (const float*)d_in[0];
    const float* rel_pos = (const float*)d_in[1];
    const float* w_qkv   = (const float*)d_in[2];
    const float* b_qkv   = (const float*)d_in[3];
    const float* w_out   = (const float*)d_in[4];
    const float* b_out   = (const float*)d_in[5];
    float* y = (float*)d_out;

    // QKV projection: 64 slabs, N=768 (12 n-tiles), M=1024 (8 m-tiles)
    gemm_k<0><<<dim3(8, 12, 64), 256>>>(w_qkv, x, b_qkv, nullptr);
    // attention: grid (hw tiles=128, b*heads=32)
    attn_k<<<dim3(128, 32), 128>>>(rel_pos);
    // output projection: N=256 (4 n-tiles) -> y in (B,T,C,H,W) layout
    gemm_k<1><<<dim3(8, 4, 64), 256>>>(w_out, nullptr, b_out, y);
}